// round 11
// baseline (speedup 1.0000x reference)
#include <cuda_runtime.h>
#include <cuda_fp16.h>
#include <cstdint>
#include <cstddef>

// ---------------- problem constants ----------------
#define S_TOK   8192
#define HDIM    1024
#define FDIM    4096
#define NEXP    8
#define NPAIR   16384              // S*K rows (one per (s,k) pair, no dedup)
#define ROWS_PAD 17408             // NPAIR + 8*127 rounded up
#define MTILE_MAX 144              // worst-case per-expert 128-row tiles (<=136)

// GEMM tile: BM=128, BN=128, BK=32, 4-stage cp.async pipeline, mma.sync core
#define APITCH 80                  // 64B row + 16B pad -> conflict-free ldmatrix
#define A_STG  (128 * APITCH)      // 10240
#define B_STG  (128 * APITCH)      // 10240
#define STAGE_BYTES (A_STG + B_STG)            // 20480
#define SMEM_TOTAL  (4 * STAGE_BYTES)          // 81920

// ---------------- device scratch (allocation-free rule) ----------------
__device__ __half g_xg  [(size_t)ROWS_PAD * HDIM];
__device__ __half g_hbuf[(size_t)ROWS_PAD * FDIM];
__device__ float  g_yh  [(size_t)ROWS_PAD * HDIM];
__device__ __half g_w1h [(size_t)NEXP * FDIM * HDIM];
__device__ __half g_w2h [(size_t)NEXP * FDIM * HDIM];
__device__ float  g_row_w[ROWS_PAD];
__device__ int    g_tok_rows[NPAIR];
__device__ int    g_cnt [NEXP];
__device__ int    g_base[NEXP];
__device__ int    g_fill[NEXP];
__device__ int    g_tile_e[MTILE_MAX];
__device__ int    g_tile_m[MTILE_MAX];
__device__ int    g_nmt;

// ---------------- PTX helpers ----------------
__device__ __forceinline__ uint32_t smem_u32(const void* p) {
    uint32_t a;
    asm("{ .reg .u64 t; cvta.to.shared.u64 t, %1; cvt.u32.u64 %0, t; }"
        : "=r"(a) : "l"(p));
    return a;
}

__device__ __forceinline__ void cp16(uint32_t dst, const void* src) {
    asm volatile("cp.async.cg.shared.global [%0], [%1], 16;"
                 :: "r"(dst), "l"(src));
}

__device__ __forceinline__ void ldsm4(uint32_t* r, uint32_t a) {
    asm volatile("ldmatrix.sync.aligned.m8n8.x4.shared.b16 {%0,%1,%2,%3}, [%4];"
                 : "=r"(r[0]), "=r"(r[1]), "=r"(r[2]), "=r"(r[3]) : "r"(a));
}

__device__ __forceinline__ void mma16816(float* c, const uint32_t* a,
                                         uint32_t b0, uint32_t b1) {
    asm volatile(
        "mma.sync.aligned.m16n8k16.row.col.f32.f16.f16.f32 "
        "{%0,%1,%2,%3}, {%4,%5,%6,%7}, {%8,%9}, {%0,%1,%2,%3};"
        : "+f"(c[0]), "+f"(c[1]), "+f"(c[2]), "+f"(c[3])
        : "r"(a[0]), "r"(a[1]), "r"(a[2]), "r"(a[3]), "r"(b0), "r"(b1));
}

// ---------------- routing kernels ----------------
__global__ void zero_cnt_kernel() {
    if (threadIdx.x < NEXP) g_cnt[threadIdx.x] = 0;
}

__global__ void count_kernel(const int* __restrict__ te) {
    int t = blockIdx.x * 256 + threadIdx.x;
    if (t < NPAIR) atomicAdd(&g_cnt[((unsigned)te[t]) & 7u], 1);
}

__global__ void sched_kernel() {
    if (threadIdx.x == 0) {
        int base = 0, nt = 0;
        for (int e = 0; e < NEXP; e++) {
            g_base[e] = base;
            g_fill[e] = 0;
            int tiles = (g_cnt[e] + 127) >> 7;
            for (int t = 0; t < tiles; t++) {
                g_tile_e[nt] = e;
                g_tile_m[nt] = base + t * 128;
                nt++;
            }
            base += tiles << 7;
        }
        g_nmt = nt;
    }
}

__global__ void fill_kernel(const int* __restrict__ te, const float* __restrict__ tw) {
    int t = blockIdx.x * 256 + threadIdx.x;
    if (t < NPAIR) {
        int e = ((unsigned)te[t]) & 7u;
        int pos = atomicAdd(&g_fill[e], 1);
        int row = g_base[e] + pos;
        g_tok_rows[t] = row;
        g_row_w[row] = tw[t];
    }
}

// gather x rows (fp32 -> fp16) into grouped buffer; one block per (s,k) pair
__global__ void gather_kernel(const float* __restrict__ x) {
    int p = blockIdx.x;
    int j = threadIdx.x;                       // float4 index within row (256)
    int row = g_tok_rows[p];
    int s = p >> 1;
    float4 v = reinterpret_cast<const float4*>(x)[(size_t)s * 256 + j];
    __half2 a = __floats2half2_rn(v.x, v.y);
    __half2 b = __floats2half2_rn(v.z, v.w);
    uint2 u = make_uint2(*(uint32_t*)&a, *(uint32_t*)&b);
    *reinterpret_cast<uint2*>(&g_xg[(size_t)row * HDIM + j * 4]) = u;
}

// fp32 -> fp16 weight convert (w1 then w2, flat over float4s)
__global__ void convert_kernel(const float* __restrict__ w1, const float* __restrict__ w2) {
    size_t i = (size_t)blockIdx.x * 256 + threadIdx.x;   // float4 index
    const size_t W1Q = (size_t)NEXP * FDIM * HDIM / 4;
    const float4* src;
    __half* dst;
    size_t off;
    if (i < W1Q) { src = (const float4*)w1; dst = g_w1h; off = i; }
    else         { src = (const float4*)w2; dst = g_w2h; off = i - W1Q; }
    float4 v = src[off];
    __half2 a = __floats2half2_rn(v.x, v.y);
    __half2 b = __floats2half2_rn(v.z, v.w);
    uint2 u = make_uint2(*(uint32_t*)&a, *(uint32_t*)&b);
    *reinterpret_cast<uint2*>(&dst[off * 4]) = u;
}

// y[s] = yh[row(s,0)] + yh[row(s,1)]   (fixed order -> deterministic)
__global__ void combine_kernel(float* __restrict__ out) {
    int s = blockIdx.x, j = threadIdx.x;
    int r0 = g_tok_rows[2 * s];
    int r1 = g_tok_rows[2 * s + 1];
    const float4* Y = reinterpret_cast<const float4*>(g_yh);
    float4 a = Y[(size_t)r0 * 256 + j];
    float4 b = Y[(size_t)r1 * 256 + j];
    reinterpret_cast<float4*>(out)[(size_t)s * 256 + j] =
        make_float4(a.x + b.x, a.y + b.y, a.z + b.z, a.w + b.w);
}

// ---------------- grouped GEMM (mma.sync + cp.async pipeline) ----------------
// mode 0: h = silu(Xg @ W1[e]^T) -> g_hbuf fp16    (lda=1024, kiter=32)
// mode 1: y = (h @ W2[e]^T) * w  -> g_yh  fp32     (lda=4096, kiter=128)
__device__ __forceinline__ void load_stage(uint32_t stg, int chunk,
                                           const __half* A, const __half* B,
                                           int lda, int tid) {
    uint32_t a_s = stg + (uint32_t)(chunk & 3) * STAGE_BYTES;
    uint32_t b_s = a_s + A_STG;
    const __half* Ap = A + chunk * 32;
    const __half* Bp = B + chunk * 32;
#pragma unroll
    for (int i = 0; i < 2; i++) {                 // A: 128 rows x 4 x 16B
        int q = i * 256 + tid;
        int r = q >> 2, c = q & 3;
        cp16(a_s + (uint32_t)(r * APITCH + c * 16), Ap + (size_t)r * lda + c * 8);
    }
#pragma unroll
    for (int i = 0; i < 2; i++) {                 // B: 128 rows x 4 x 16B
        int q = i * 256 + tid;
        int r = q >> 2, c = q & 3;
        cp16(b_s + (uint32_t)(r * APITCH + c * 16), Bp + (size_t)r * lda + c * 8);
    }
    asm volatile("cp.async.commit_group;" ::: "memory");
}

__global__ void __launch_bounds__(256, 2) gemm_kernel(int mode) {
    int mt_idx = blockIdx.y;
    if (mt_idx >= g_nmt) return;

    const int lda   = mode ? FDIM : HDIM;
    const int kiter = mode ? (FDIM / 32) : (HDIM / 32);
    int m_base = g_tile_m[mt_idx];
    int n_base = blockIdx.x * 128;
    const __half* A = (mode ? g_hbuf : g_xg) + (size_t)m_base * lda;
    const __half* B = (mode ? g_w2h : g_w1h)
                      + (size_t)g_tile_e[mt_idx] * ((size_t)FDIM * HDIM)
                      + (size_t)n_base * lda;

    int tid = threadIdx.x;
    int wid = tid >> 5, lid = tid & 31;
    int warp_m = wid & 1;          // 2 along M  -> 64 rows each
    int warp_n = wid >> 1;         // 4 along N  -> 32 cols each

    extern __shared__ char smem[];
    uint32_t stg = smem_u32(smem);

    // ldmatrix lane addressing (A and B patterns)
    int ar = (lid & 7) + ((lid >> 3) & 1) * 8;   // row within 16-row tile
    int ac = (lid >> 4) & 1;                     // 16B k-chunk select
    int br = (lid & 7) + ((lid >> 4) & 1) * 8;   // row within 16-row n-pair
    int bc = (lid >> 3) & 1;

    float acc[4][4][4];
#pragma unroll
    for (int mt = 0; mt < 4; mt++)
#pragma unroll
        for (int nt = 0; nt < 4; nt++)
#pragma unroll
            for (int i = 0; i < 4; i++) acc[mt][nt][i] = 0.0f;

    // prologue: 3 stages in flight
    load_stage(stg, 0, A, B, lda, tid);
    load_stage(stg, 1, A, B, lda, tid);
    load_stage(stg, 2, A, B, lda, tid);

    for (int k = 0; k < kiter; k++) {
        if (k + 3 <= kiter - 1)      asm volatile("cp.async.wait_group 2;" ::: "memory");
        else if (k + 2 <= kiter - 1) asm volatile("cp.async.wait_group 1;" ::: "memory");
        else                         asm volatile("cp.async.wait_group 0;" ::: "memory");
        __syncthreads();

        if (k + 3 < kiter) load_stage(stg, k + 3, A, B, lda, tid);

        uint32_t a_s = stg + (uint32_t)(k & 3) * STAGE_BYTES
                     + (uint32_t)(warp_m * 64 * APITCH);
        uint32_t b_s = stg + (uint32_t)(k & 3) * STAGE_BYTES + A_STG
                     + (uint32_t)(warp_n * 32 * APITCH);

#pragma unroll
        for (int ks = 0; ks < 2; ks++) {          // two k16 steps per BK=32
            uint32_t af[4][4];
#pragma unroll
            for (int mt = 0; mt < 4; mt++)
                ldsm4(af[mt], a_s + (uint32_t)((mt * 16 + ar) * APITCH
                                               + ks * 32 + ac * 16));
            uint32_t bf[2][4];                    // each x4 covers 2 n-tiles
#pragma unroll
            for (int np = 0; np < 2; np++)
                ldsm4(bf[np], b_s + (uint32_t)((np * 16 + br) * APITCH
                                               + ks * 32 + bc * 16));
#pragma unroll
            for (int mt = 0; mt < 4; mt++) {
#pragma unroll
                for (int nt = 0; nt < 4; nt++) {
                    mma16816(acc[mt][nt], af[mt],
                             bf[nt >> 1][(nt & 1) * 2],
                             bf[nt >> 1][(nt & 1) * 2 + 1]);
                }
            }
        }
    }
    __syncthreads();

    // ---------------- epilogue ----------------
    int rbase = m_base + warp_m * 64;
    int cbase = n_base + warp_n * 32;
    int rl = lid >> 2;                  // 0..7
    int cl = (lid & 3) * 2;             // 0,2,4,6

    if (mode == 0) {
#pragma unroll
        for (int mt = 0; mt < 4; mt++) {
            int r0 = rbase + mt * 16 + rl;
#pragma unroll
            for (int nt = 0; nt < 4; nt++) {
                int c = cbase + nt * 8 + cl;
                float v0 = acc[mt][nt][0], v1 = acc[mt][nt][1];
                float v2 = acc[mt][nt][2], v3 = acc[mt][nt][3];
                v0 = v0 / (1.0f + __expf(-v0));
                v1 = v1 / (1.0f + __expf(-v1));
                v2 = v2 / (1.0f + __expf(-v2));
                v3 = v3 / (1.0f + __expf(-v3));
                __half2 h01 = __floats2half2_rn(v0, v1);
                __half2 h23 = __floats2half2_rn(v2, v3);
                *reinterpret_cast<__half2*>(&g_hbuf[(size_t)r0 * FDIM + c]) = h01;
                *reinterpret_cast<__half2*>(&g_hbuf[(size_t)(r0 + 8) * FDIM + c]) = h23;
            }
        }
    } else {
#pragma unroll
        for (int mt = 0; mt < 4; mt++) {
            int r0 = rbase + mt * 16 + rl;
            float w0 = g_row_w[r0];
            float w1 = g_row_w[r0 + 8];
#pragma unroll
            for (int nt = 0; nt < 4; nt++) {
                int c = cbase + nt * 8 + cl;
                float2 p0 = make_float2(acc[mt][nt][0] * w0, acc[mt][nt][1] * w0);
                float2 p1 = make_float2(acc[mt][nt][2] * w1, acc[mt][nt][3] * w1);
                *reinterpret_cast<float2*>(&g_yh[(size_t)r0 * HDIM + c]) = p0;
                *reinterpret_cast<float2*>(&g_yh[(size_t)(r0 + 8) * HDIM + c]) = p1;
            }
        }
    }
}

// ---------------- launch ----------------
extern "C" void kernel_launch(void* const* d_in, const int* in_sizes, int n_in,
                              void* d_out, int out_size) {
    const float* x  = (const float*)d_in[0];
    const int*   te = (const int*)d_in[1];
    const float* tw = (const float*)d_in[2];
    const float* w1 = (const float*)d_in[3];
    const float* w2 = (const float*)d_in[4];
    float* out = (float*)d_out;

    cudaFuncSetAttribute(gemm_kernel, cudaFuncAttributeMaxDynamicSharedMemorySize,
                         SMEM_TOTAL);

    zero_cnt_kernel<<<1, 32>>>();
    count_kernel<<<NPAIR / 256, 256>>>(te);
    sched_kernel<<<1, 32>>>();
    fill_kernel<<<NPAIR / 256, 256>>>(te, tw);
    gather_kernel<<<NPAIR, 256>>>(x);
    convert_kernel<<<65536, 256>>>(w1, w2);   // 2*8*4096*1024/4 float4s
    gemm_kernel<<<dim3(FDIM / 128, MTILE_MAX), 256, SMEM_TOTAL>>>(0);
    gemm_kernel<<<dim3(HDIM / 128, MTILE_MAX), 256, SMEM_TOTAL>>>(1);
    combine_kernel<<<S_TOK, 256>>>(out);
}

// round 12
// speedup vs baseline: 1.2097x; 1.2097x over previous
#include <cuda_runtime.h>
#include <cuda_fp16.h>
#include <cstdint>
#include <cstddef>

// ---------------- problem constants ----------------
#define S_TOK   8192
#define HDIM    1024
#define FDIM    4096
#define NEXP    8
#define NPAIR   16384              // S*K rows (one per (s,k) pair, no dedup)
#define ROWS_PAD 17408             // NPAIR + 8*127 rounded up
#define MTILE_MAX 144              // worst-case per-expert 128-row tiles (<=135)
#define CONV_ROWS 64               // extra grid.y rows in gemm1 that convert w2

// GEMM tile: BM=128, BN=128, BK=64, 3-stage cp.async pipeline, mma.sync core
// smem stage: A 128x128B + B 128x128B, XOR-swizzled 16B chunks (chunk ^= row&7)
#define A_STG  16384
#define STAGE_BYTES 32768
#define SMEM_TOTAL  (3 * STAGE_BYTES)          // 98304

// ---------------- device scratch (allocation-free rule) ----------------
__device__ __half g_xg  [(size_t)ROWS_PAD * HDIM];
__device__ __half g_hbuf[(size_t)ROWS_PAD * FDIM];
__device__ float  g_yh  [(size_t)ROWS_PAD * HDIM];
__device__ __half g_w1h [(size_t)NEXP * FDIM * HDIM];
__device__ __half g_w2h [(size_t)NEXP * FDIM * HDIM];
__device__ float  g_row_w[ROWS_PAD];
__device__ int    g_tok_rows[NPAIR];
__device__ int    g_base[NEXP];
__device__ int    g_fill[NEXP];
__device__ int    g_tile_e[MTILE_MAX];
__device__ int    g_tile_m[MTILE_MAX];
__device__ int    g_nmt;

// ---------------- PTX helpers ----------------
__device__ __forceinline__ uint32_t smem_u32(const void* p) {
    uint32_t a;
    asm("{ .reg .u64 t; cvta.to.shared.u64 t, %1; cvt.u32.u64 %0, t; }"
        : "=r"(a) : "l"(p));
    return a;
}

__device__ __forceinline__ void cp16(uint32_t dst, const void* src) {
    asm volatile("cp.async.cg.shared.global [%0], [%1], 16;"
                 :: "r"(dst), "l"(src));
}

__device__ __forceinline__ void ldsm4(uint32_t* r, uint32_t a) {
    asm volatile("ldmatrix.sync.aligned.m8n8.x4.shared.b16 {%0,%1,%2,%3}, [%4];"
                 : "=r"(r[0]), "=r"(r[1]), "=r"(r[2]), "=r"(r[3]) : "r"(a));
}

__device__ __forceinline__ void mma16816(float* c, const uint32_t* a,
                                         uint32_t b0, uint32_t b1) {
    asm volatile(
        "mma.sync.aligned.m16n8k16.row.col.f32.f16.f16.f32 "
        "{%0,%1,%2,%3}, {%4,%5,%6,%7}, {%8,%9}, {%0,%1,%2,%3};"
        : "+f"(c[0]), "+f"(c[1]), "+f"(c[2]), "+f"(c[3])
        : "r"(a[0]), "r"(a[1]), "r"(a[2]), "r"(a[3]), "r"(b0), "r"(b1));
}

// ---------------- routing (single block: zero + count + schedule) ----------------
__global__ void routing_kernel(const int* __restrict__ te) {
    __shared__ int scnt[NEXP];
    int tid = threadIdx.x;
    if (tid < NEXP) scnt[tid] = 0;
    __syncthreads();
    for (int t = tid; t < NPAIR; t += 256)
        atomicAdd(&scnt[((unsigned)te[t]) & 7u], 1);
    __syncthreads();
    if (tid == 0) {
        int base = 0, nt = 0;
        for (int e = 0; e < NEXP; e++) {
            g_base[e] = base;
            g_fill[e] = 0;
            int tiles = (scnt[e] + 127) >> 7;
            for (int t = 0; t < tiles; t++) {
                g_tile_e[nt] = e;
                g_tile_m[nt] = base + t * 128;
                nt++;
            }
            base += tiles << 7;
        }
        g_nmt = nt;
    }
}

__global__ void fill_kernel(const int* __restrict__ te, const float* __restrict__ tw) {
    int t = blockIdx.x * 256 + threadIdx.x;
    if (t < NPAIR) {
        int e = ((unsigned)te[t]) & 7u;
        int pos = atomicAdd(&g_fill[e], 1);
        int row = g_base[e] + pos;
        g_tok_rows[t] = row;
        g_row_w[row] = tw[t];
    }
}

// gather x rows (fp32 -> fp16) into grouped buffer; one block per (s,k) pair
__global__ void gather_kernel(const float* __restrict__ x) {
    int p = blockIdx.x;
    int j = threadIdx.x;                       // float4 index within row (256)
    int row = g_tok_rows[p];
    int s = p >> 1;
    float4 v = reinterpret_cast<const float4*>(x)[(size_t)s * 256 + j];
    __half2 a = __floats2half2_rn(v.x, v.y);
    __half2 b = __floats2half2_rn(v.z, v.w);
    uint2 u = make_uint2(*(uint32_t*)&a, *(uint32_t*)&b);
    *reinterpret_cast<uint2*>(&g_xg[(size_t)row * HDIM + j * 4]) = u;
}

// fp32 -> fp16 convert for w1 only (w2 is converted inside the gemm1 launch)
__global__ void convert_w1_kernel(const float* __restrict__ w1) {
    size_t i = (size_t)blockIdx.x * 256 + threadIdx.x;   // float4 index
    float4 v = reinterpret_cast<const float4*>(w1)[i];
    __half2 a = __floats2half2_rn(v.x, v.y);
    __half2 b = __floats2half2_rn(v.z, v.w);
    uint2 u = make_uint2(*(uint32_t*)&a, *(uint32_t*)&b);
    *reinterpret_cast<uint2*>(&g_w1h[i * 4]) = u;
}

// y[s] = yh[row(s,0)] + yh[row(s,1)]   (fixed order -> deterministic)
__global__ void combine_kernel(float* __restrict__ out) {
    int s = blockIdx.x, j = threadIdx.x;
    int r0 = g_tok_rows[2 * s];
    int r1 = g_tok_rows[2 * s + 1];
    const float4* Y = reinterpret_cast<const float4*>(g_yh);
    float4 a = Y[(size_t)r0 * 256 + j];
    float4 b = Y[(size_t)r1 * 256 + j];
    reinterpret_cast<float4*>(out)[(size_t)s * 256 + j] =
        make_float4(a.x + b.x, a.y + b.y, a.z + b.z, a.w + b.w);
}

// ---------------- grouped GEMM (mma.sync + cp.async, BK=64, 3 stages) ----------------
// mode 0: h = silu(Xg @ W1[e]^T) -> g_hbuf fp16    (lda=1024, kiter=16)
//         plus CONV_ROWS extra grid.y rows converting w2 fp32->fp16
// mode 1: y = (h @ W2[e]^T) * w  -> g_yh  fp32     (lda=4096, kiter=64)
__device__ __forceinline__ void load_stage(uint32_t stg, int chunk,
                                           const __half* A, const __half* B,
                                           int lda, int tid) {
    uint32_t base = stg + (uint32_t)(chunk % 3) * STAGE_BYTES;
    const __half* Ap = A + chunk * 64;
    const __half* Bp = B + chunk * 64;
#pragma unroll
    for (int i = 0; i < 4; i++) {                 // A: 128 rows x 8 x 16B chunks
        int q = i * 256 + tid;
        int r = q >> 3, c = q & 7;
        uint32_t dst = base + (uint32_t)(r * 128 + ((c ^ (r & 7)) << 4));
        cp16(dst, Ap + (size_t)r * lda + c * 8);
    }
#pragma unroll
    for (int i = 0; i < 4; i++) {                 // B: 128 rows x 8 x 16B chunks
        int q = i * 256 + tid;
        int r = q >> 3, c = q & 7;
        uint32_t dst = base + A_STG + (uint32_t)(r * 128 + ((c ^ (r & 7)) << 4));
        cp16(dst, Bp + (size_t)r * lda + c * 8);
    }
    asm volatile("cp.async.commit_group;" ::: "memory");
}

__global__ void __launch_bounds__(256, 2) gemm_kernel(int mode, const float* w2src) {
    // ---- fused w2 converter role (layer-1 launch only) ----
    if (mode == 0 && blockIdx.y >= MTILE_MAX) {
        size_t cid = (size_t)(blockIdx.y - MTILE_MAX) * gridDim.x + blockIdx.x;
        size_t tbase = cid * 256 + threadIdx.x;            // 0 .. 524287
        const float4* src = reinterpret_cast<const float4*>(w2src);
#pragma unroll 4
        for (int j = 0; j < 16; j++) {                     // 524288*16 = 8388608 float4
            size_t idx = tbase + (size_t)j * (CONV_ROWS * 32 * 256);
            float4 v = src[idx];
            __half2 a = __floats2half2_rn(v.x, v.y);
            __half2 b = __floats2half2_rn(v.z, v.w);
            uint2 u = make_uint2(*(uint32_t*)&a, *(uint32_t*)&b);
            *reinterpret_cast<uint2*>(&g_w2h[idx * 4]) = u;
        }
        return;
    }

    int mt_idx = blockIdx.y;
    if (mt_idx >= g_nmt) return;

    const int lda   = mode ? FDIM : HDIM;
    const int kiter = mode ? (FDIM / 64) : (HDIM / 64);
    int m_base = g_tile_m[mt_idx];
    int n_base = blockIdx.x * 128;
    const __half* A = (mode ? g_hbuf : g_xg) + (size_t)m_base * lda;
    const __half* B = (mode ? g_w2h : g_w1h)
                      + (size_t)g_tile_e[mt_idx] * ((size_t)FDIM * HDIM)
                      + (size_t)n_base * lda;

    int tid = threadIdx.x;
    int wid = tid >> 5, lid = tid & 31;
    int warp_m = wid & 1;          // 2 along M  -> 64 rows each
    int warp_n = wid >> 1;         // 4 along N  -> 32 cols each

    extern __shared__ char smem[];
    uint32_t stg = smem_u32(smem);

    // ldmatrix lane addressing (same fragment mapping as the passing R10 kernel)
    int ar = (lid & 7) + ((lid >> 3) & 1) * 8;   // row within 16-row tile
    int ac = (lid >> 4) & 1;                     // 16B k-chunk select
    int br = (lid & 7) + ((lid >> 4) & 1) * 8;   // row within 16-row n-pair
    int bc = (lid >> 3) & 1;

    float acc[4][4][4];
#pragma unroll
    for (int mt = 0; mt < 4; mt++)
#pragma unroll
        for (int nt = 0; nt < 4; nt++)
#pragma unroll
            for (int i = 0; i < 4; i++) acc[mt][nt][i] = 0.0f;

    // prologue: 2 stages in flight
    load_stage(stg, 0, A, B, lda, tid);
    load_stage(stg, 1, A, B, lda, tid);

    for (int k = 0; k < kiter; k++) {
        if (k + 2 < kiter) asm volatile("cp.async.wait_group 1;" ::: "memory");
        else               asm volatile("cp.async.wait_group 0;" ::: "memory");
        __syncthreads();

        if (k + 2 < kiter) load_stage(stg, k + 2, A, B, lda, tid);

        uint32_t a_s = stg + (uint32_t)(k % 3) * STAGE_BYTES;
        uint32_t b_s = a_s + A_STG;

#pragma unroll
        for (int ks = 0; ks < 4; ks++) {          // four k16 steps per BK=64
            uint32_t af[4][4];
#pragma unroll
            for (int mt = 0; mt < 4; mt++) {
                int row = warp_m * 64 + mt * 16 + ar;
                int ch  = (ks * 2 + ac) ^ (row & 7);
                ldsm4(af[mt], a_s + (uint32_t)(row * 128 + (ch << 4)));
            }
            uint32_t bf[2][4];                    // each x4 covers 2 n-tiles
#pragma unroll
            for (int np = 0; np < 2; np++) {
                int row = warp_n * 32 + np * 16 + br;
                int ch  = (ks * 2 + bc) ^ (row & 7);
                ldsm4(bf[np], b_s + (uint32_t)(row * 128 + (ch << 4)));
            }
#pragma unroll
            for (int mt = 0; mt < 4; mt++) {
#pragma unroll
                for (int nt = 0; nt < 4; nt++) {
                    mma16816(acc[mt][nt], af[mt],
                             bf[nt >> 1][(nt & 1) * 2],
                             bf[nt >> 1][(nt & 1) * 2 + 1]);
                }
            }
        }
    }
    __syncthreads();

    // ---------------- epilogue ----------------
    int rbase = m_base + warp_m * 64;
    int cbase = n_base + warp_n * 32;
    int rl = lid >> 2;                  // 0..7
    int cl = (lid & 3) * 2;             // 0,2,4,6

    if (mode == 0) {
#pragma unroll
        for (int mt = 0; mt < 4; mt++) {
            int r0 = rbase + mt * 16 + rl;
#pragma unroll
            for (int nt = 0; nt < 4; nt++) {
                int c = cbase + nt * 8 + cl;
                float v0 = acc[mt][nt][0], v1 = acc[mt][nt][1];
                float v2 = acc[mt][nt][2], v3 = acc[mt][nt][3];
                v0 = v0 / (1.0f + __expf(-v0));
                v1 = v1 / (1.0f + __expf(-v1));
                v2 = v2 / (1.0f + __expf(-v2));
                v3 = v3 / (1.0f + __expf(-v3));
                __half2 h01 = __floats2half2_rn(v0, v1);
                __half2 h23 = __floats2half2_rn(v2, v3);
                *reinterpret_cast<__half2*>(&g_hbuf[(size_t)r0 * FDIM + c]) = h01;
                *reinterpret_cast<__half2*>(&g_hbuf[(size_t)(r0 + 8) * FDIM + c]) = h23;
            }
        }
    } else {
#pragma unroll
        for (int mt = 0; mt < 4; mt++) {
            int r0 = rbase + mt * 16 + rl;
            float w0 = g_row_w[r0];
            float w1 = g_row_w[r0 + 8];
#pragma unroll
            for (int nt = 0; nt < 4; nt++) {
                int c = cbase + nt * 8 + cl;
                float2 p0 = make_float2(acc[mt][nt][0] * w0, acc[mt][nt][1] * w0);
                float2 p1 = make_float2(acc[mt][nt][2] * w1, acc[mt][nt][3] * w1);
                *reinterpret_cast<float2*>(&g_yh[(size_t)r0 * HDIM + c]) = p0;
                *reinterpret_cast<float2*>(&g_yh[(size_t)(r0 + 8) * HDIM + c]) = p1;
            }
        }
    }
}

// ---------------- launch ----------------
extern "C" void kernel_launch(void* const* d_in, const int* in_sizes, int n_in,
                              void* d_out, int out_size) {
    const float* x  = (const float*)d_in[0];
    const int*   te = (const int*)d_in[1];
    const float* tw = (const float*)d_in[2];
    const float* w1 = (const float*)d_in[3];
    const float* w2 = (const float*)d_in[4];
    float* out = (float*)d_out;

    cudaFuncSetAttribute(gemm_kernel, cudaFuncAttributeMaxDynamicSharedMemorySize,
                         SMEM_TOTAL);

    routing_kernel<<<1, 256>>>(te);
    fill_kernel<<<NPAIR / 256, 256>>>(te, tw);
    gather_kernel<<<NPAIR, 256>>>(x);
    convert_w1_kernel<<<32768, 256>>>(w1);    // 8*4096*1024/4 float4s
    // layer-1 GEMM + fused w2 conversion (extra grid.y rows)
    gemm_kernel<<<dim3(FDIM / 128, MTILE_MAX + CONV_ROWS), 256, SMEM_TOTAL>>>(0, w2);
    gemm_kernel<<<dim3(HDIM / 128, MTILE_MAX), 256, SMEM_TOTAL>>>(1, w2);
    combine_kernel<<<S_TOK, 256>>>(out);
}